// round 11
// baseline (speedup 1.0000x reference)
#include <cuda_runtime.h>
#include <cuda_bf16.h>
#include <cstdint>
#include <math.h>

#define NTOK 4096
#define DDIM 768
#define HDIM 1536
#define NE   6

// ---------------- device scratch (fp8 = unsigned char storage) ----------------
__device__ int   g_perm[NTOK];
__device__ int   g_gstart[NE + 1];
__device__ float g_alpha[NE];
__device__ unsigned char g_xg[(size_t)NTOK * DDIM];          // x fp8, perm order, k-major
__device__ unsigned char g_h [(size_t)NTOK * HDIM];          // hidden fp8, perm order, k-major
__device__ unsigned char g_W1t[(size_t)NE * HDIM * DDIM];    // 32*W1 fp8, [e][h][d] n-major
__device__ unsigned char g_W2t[(size_t)NE * DDIM * HDIM];    // 32*W2 fp8, [e][d][h] n-major
__device__ float g_pre[(size_t)NTOK * DDIM];                 // x + alpha*r, token order

// ---------------- asm helpers ----------------
__device__ __forceinline__ void cp_async16(void* smem, const void* g, bool pred) {
    uint32_t s = (uint32_t)__cvta_generic_to_shared(smem);
    int sz = pred ? 16 : 0;   // src-size 0 -> 16B zero-fill
    asm volatile("cp.async.cg.shared.global [%0], [%1], 16, %2;\n" :: "r"(s), "l"(g), "r"(sz));
}
#define CP_COMMIT() asm volatile("cp.async.commit_group;\n" ::: "memory")
#define CP_WAIT1()  asm volatile("cp.async.wait_group 1;\n" ::: "memory")

__device__ __forceinline__ void ldsm_x4(uint32_t& r0, uint32_t& r1, uint32_t& r2, uint32_t& r3,
                                        uint32_t addr) {
    asm volatile("ldmatrix.sync.aligned.m8n8.x4.shared.b16 {%0,%1,%2,%3}, [%4];"
                 : "=r"(r0), "=r"(r1), "=r"(r2), "=r"(r3) : "r"(addr));
}

// fp8 e4m3 MMA: D(16x8,f32) += A(16x32,e4m3) * B(32x8,e4m3)
__device__ __forceinline__ void mma_fp8(float* c, const uint32_t* a, const uint32_t* b) {
    asm volatile(
        "mma.sync.aligned.m16n8k32.row.col.f32.e4m3.e4m3.f32 "
        "{%0,%1,%2,%3}, {%4,%5,%6,%7}, {%8,%9}, {%0,%1,%2,%3};\n"
        : "+f"(c[0]), "+f"(c[1]), "+f"(c[2]), "+f"(c[3])
        : "r"(a[0]), "r"(a[1]), "r"(a[2]), "r"(a[3]), "r"(b[0]), "r"(b[1]));
}

// pack two floats into e4m3x2 (lo -> byte0, hi -> byte1)
__device__ __forceinline__ unsigned short cvt_fp8x2(float lo, float hi) {
    unsigned short r;
    asm("cvt.rn.satfinite.e4m3x2.f32 %0, %1, %2;" : "=h"(r) : "f"(hi), "f"(lo));
    return r;
}

// ---------------- prep: sort tokens by group ----------------
__global__ void prep_kernel(const int* __restrict__ ids,
                            const int* __restrict__ e2g,
                            const float* __restrict__ raw_alpha,
                            int T) {
    __shared__ int cnt[NE];
    __shared__ int cur[NE];
    __shared__ unsigned char gid_s[NTOK];
    int tid = threadIdx.x;
    if (tid < NE) cnt[tid] = 0;
    __syncthreads();
    for (int i = tid; i < NTOK; i += blockDim.x) {
        int ty = ids[i];
        ty = ty < 0 ? 0 : (ty > T - 1 ? T - 1 : ty);
        int gd = e2g[ty];
        gid_s[i] = (unsigned char)gd;
        atomicAdd(&cnt[gd], 1);
    }
    __syncthreads();
    if (tid == 0) {
        int acc = 0;
        for (int e = 0; e < NE; e++) { g_gstart[e] = acc; cur[e] = acc; acc += cnt[e]; }
        g_gstart[NE] = acc;
    }
    __syncthreads();
    for (int i = tid; i < NTOK; i += blockDim.x) {
        int pos = atomicAdd(&cur[gid_s[i]], 1);
        g_perm[pos] = i;
    }
    if (tid < NE) g_alpha[tid] = 0.05f / (1.0f + expf(-raw_alpha[tid]));
}

// ---------------- weight transpose + fp32 -> fp8 (x32 scale) ----------------
// in: [E][R][C] fp32 (C contiguous) -> out: [E][C][R] fp8 (R contiguous), value*32
__global__ void transpose_cvt_kernel(const float* __restrict__ in, int R, int C, int which) {
    __shared__ float tile[32][33];
    unsigned char* out = which ? g_W2t : g_W1t;
    int e  = blockIdx.z;
    int c0 = blockIdx.x * 32, r0 = blockIdx.y * 32;
    const float* inp = in + (size_t)e * R * C;
    unsigned char* op = out + (size_t)e * R * C;
    int tx = threadIdx.x, ty = threadIdx.y;   // (32, 8)
    #pragma unroll
    for (int j = ty; j < 32; j += 8)
        tile[j][tx] = inp[(size_t)(r0 + j) * C + c0 + tx];
    __syncthreads();
    int tid = ty * 32 + tx;
    int orow = tid >> 3, oc = tid & 7;   // output row (c-local), 4-elem chunk
    float f0 = tile[oc * 4 + 0][orow] * 32.f;
    float f1 = tile[oc * 4 + 1][orow] * 32.f;
    float f2 = tile[oc * 4 + 2][orow] * 32.f;
    float f3 = tile[oc * 4 + 3][orow] * 32.f;
    uint32_t u = (uint32_t)cvt_fp8x2(f0, f1) | ((uint32_t)cvt_fp8x2(f2, f3) << 16);
    *reinterpret_cast<uint32_t*>(op + (size_t)(c0 + orow) * R + r0 + oc * 4) = u;
}

// ---------------- gather x rows in perm order, fp32 -> fp8 ----------------
// 768 blocks x 256 threads; 16 fp8 per thread (4096 rows x 48 chunks)
__global__ void gather_kernel(const float* __restrict__ x) {
    int idx = blockIdx.x * 256 + threadIdx.x;
    int p = idx / 48, j = idx % 48;
    int t = g_perm[p];
    const float4* src = reinterpret_cast<const float4*>(x + (size_t)t * DDIM) + j * 4;
    uint32_t w[4];
    #pragma unroll
    for (int q = 0; q < 4; q++) {
        float4 v = src[q];
        w[q] = (uint32_t)cvt_fp8x2(v.x, v.y) | ((uint32_t)cvt_fp8x2(v.z, v.w) << 16);
    }
    uint4 o = make_uint4(w[0], w[1], w[2], w[3]);
    *(reinterpret_cast<uint4*>(g_xg + (size_t)p * DDIM) + j) = o;
}

// ---------------- grouped FP8 GEMM: BM=64 BN=128 BK=64, 3-stage cp.async ----------------
// A fp8 k-major, B fp8 n-major [n][k]; both fragments via plain ldmatrix (b16 over fp8 bytes).
// EPI2 == false : g_h[p,:] = fp8(relu(acc/32 + b1))
// EPI2 == true  : g_pre[t,:] = x[t,:] + alpha[g] * (acc/32 + b2)
template<int K, bool EPI2>
__global__ void __launch_bounds__(256, 3) gemm_kernel(
    const float* __restrict__ bias,        // [E][NTOT] fp32
    const float* __restrict__ x)
{
    constexpr int BM = 64, BN = 128, BK = 64;
    constexpr int P = 80;                              // smem row pitch (bytes), conflict-free
    constexpr int NTOT = EPI2 ? DDIM : HDIM;
    constexpr int NIT  = K / BK;
    constexpr int A_BYTES = BM * P;                    // 5120
    constexpr int STAGE_BYTES = A_BYTES + BN * P;      // 15360
    constexpr int B_OFF = A_BYTES;

    extern __shared__ __align__(16) unsigned char smem_raw[];
    uint32_t sbase = (uint32_t)__cvta_generic_to_shared(smem_raw);

    const unsigned char* A  = EPI2 ? g_h   : g_xg;
    const unsigned char* Bw = EPI2 ? g_W2t : g_W1t;

    int g     = blockIdx.z;
    int start = g_gstart[g];
    int cnt   = g_gstart[g + 1] - start;
    int m0    = blockIdx.x * BM;
    if (m0 >= cnt) return;
    int n0 = blockIdx.y * BN;
    const unsigned char* Bg = Bw + (size_t)g * NTOT * K;   // [n][k]
    const unsigned char* Ag = A + (size_t)start * K;

    int tid  = threadIdx.x;
    int warp = tid >> 5, lane = tid & 31;
    int wm = (warp & 1) * 32;       // 2 warps over M
    int wn = (warp >> 1) * 32;      // 4 warps over N
    int lrow = lane >> 2;
    int lcol = (lane & 3) * 2;

    // ldmatrix lane offsets (bytes within stage)
    // A (x4 per mi per ks): matrices = [rows0-7 klo][rows8-15 klo][rows0-7 khi][rows8-15 khi]
    uint32_t aOff[2];
    #pragma unroll
    for (int mi = 0; mi < 2; mi++)
        aOff[mi] = (uint32_t)((wm + mi * 16 + ((lane >> 3) & 1) * 8 + (lane & 7)) * P
                              + (lane >> 4) * 16);
    // B (x4 per j): matrices = [nb0 klo][nb0 khi][nb1 klo][nb1 khi]; nb pairs per j
    uint32_t bOff[2];
    #pragma unroll
    for (int j = 0; j < 2; j++)
        bOff[j] = (uint32_t)(B_OFF + (wn + j * 16 + ((lane >> 4) & 1) * 8 + (lane & 7)) * P
                             + ((lane >> 3) & 1) * 16);

    auto load_stage = [&](int s, int k0) {
        unsigned char* As = smem_raw + s * STAGE_BYTES;
        unsigned char* Bs = As + B_OFF;
        // A: 64 rows x 4 chunks of 16B = 256, 1/thread
        {
            int r = tid >> 2, v = tid & 3;
            bool p = (m0 + r) < cnt;
            int rr = p ? (m0 + r) : 0;
            cp_async16(As + r * P + v * 16, Ag + (size_t)rr * K + k0 + v * 16, p);
        }
        // B: 128 rows x 4 chunks of 16B = 512, 2/thread
        #pragma unroll
        for (int i = 0; i < 2; i++) {
            int c = tid + i * 256;
            int r = c >> 2, v = c & 3;
            cp_async16(Bs + r * P + v * 16,
                       Bg + (size_t)(n0 + r) * K + k0 + v * 16, true);
        }
    };

    float acc[2][4][4];
    #pragma unroll
    for (int mi = 0; mi < 2; mi++)
        #pragma unroll
        for (int ni = 0; ni < 4; ni++)
            #pragma unroll
            for (int qq = 0; qq < 4; qq++) acc[mi][ni][qq] = 0.f;

    load_stage(0, 0);
    CP_COMMIT();
    load_stage(1, BK);
    CP_COMMIT();

    for (int it = 0; it < NIT; it++) {
        CP_WAIT1();
        __syncthreads();

        if (it + 2 < NIT) load_stage((it + 2) % 3, (it + 2) * BK);
        CP_COMMIT();

        uint32_t stg = sbase + (uint32_t)((it % 3) * STAGE_BYTES);
        #pragma unroll
        for (int ks = 0; ks < 2; ks++) {           // two k32 steps per BK=64
            uint32_t af[2][4], bq[2][4];
            #pragma unroll
            for (int mi = 0; mi < 2; mi++)
                ldsm_x4(af[mi][0], af[mi][1], af[mi][2], af[mi][3],
                        stg + aOff[mi] + ks * 32);
            #pragma unroll
            for (int j = 0; j < 2; j++)
                ldsm_x4(bq[j][0], bq[j][1], bq[j][2], bq[j][3],
                        stg + bOff[j] + ks * 32);
            #pragma unroll
            for (int mi = 0; mi < 2; mi++)
                #pragma unroll
                for (int ni = 0; ni < 4; ni++)
                    mma_fp8(acc[mi][ni], af[mi], &bq[ni >> 1][(ni & 1) * 2]);
        }
    }

    // ---- epilogue (weights carried x32 -> descale) ----
    constexpr float INV32 = 0.03125f;
    float alpha = EPI2 ? g_alpha[g] : 0.f;
    const float* bg = bias + (size_t)g * NTOT;
    #pragma unroll
    for (int mi = 0; mi < 2; mi++) {
        #pragma unroll
        for (int half = 0; half < 2; half++) {
            int rloc = wm + mi * 16 + lrow + half * 8;
            int grow = m0 + rloc;
            if (grow >= cnt) continue;
            #pragma unroll
            for (int ni = 0; ni < 4; ni++) {
                int c = n0 + wn + ni * 8 + lcol;
                float v0 = acc[mi][ni][half * 2 + 0] * INV32 + bg[c];
                float v1 = acc[mi][ni][half * 2 + 1] * INV32 + bg[c + 1];
                if (!EPI2) {
                    v0 = fmaxf(v0, 0.f);
                    v1 = fmaxf(v1, 0.f);
                    *reinterpret_cast<unsigned short*>(
                        g_h + (size_t)(start + grow) * HDIM + c) = cvt_fp8x2(v0, v1);
                } else {
                    int t = g_perm[start + grow];
                    float2 xv = *reinterpret_cast<const float2*>(x + (size_t)t * DDIM + c);
                    float2 o;
                    o.x = xv.x + alpha * v0;
                    o.y = xv.y + alpha * v1;
                    *reinterpret_cast<float2*>(&g_pre[(size_t)t * DDIM + c]) = o;
                }
            }
        }
    }
}

// ---------------- normalize ----------------
__global__ void normalize_kernel(float* __restrict__ out) {
    int t = blockIdx.x;
    const float4* pr = reinterpret_cast<const float4*>(g_pre) + (size_t)t * 192;
    float4 v = pr[threadIdx.x];
    float s = v.x * v.x + v.y * v.y + v.z * v.z + v.w * v.w;
    #pragma unroll
    for (int o = 16; o > 0; o >>= 1) s += __shfl_xor_sync(0xffffffffu, s, o);
    __shared__ float red[6];
    int warp = threadIdx.x >> 5, lane = threadIdx.x & 31;
    if (lane == 0) red[warp] = s;
    __syncthreads();
    if (threadIdx.x == 0) {
        float z = 0.f;
        #pragma unroll
        for (int i = 0; i < 6; i++) z += red[i];
        red[0] = 1.f / fmaxf(sqrtf(z), 1e-12f);
    }
    __syncthreads();
    float inv = red[0];
    float4 o;
    o.x = v.x * inv; o.y = v.y * inv; o.z = v.z * inv; o.w = v.w * inv;
    reinterpret_cast<float4*>(out)[(size_t)t * 192 + threadIdx.x] = o;
}

// ---------------- launch: forked-stream graph ----------------
extern "C" void kernel_launch(void* const* d_in, const int* in_sizes, int n_in,
                              void* d_out, int out_size) {
    const float* x         = (const float*)d_in[0];
    const int*   ids       = (const int*)d_in[1];
    const float* W1        = (const float*)d_in[2];
    const float* b1        = (const float*)d_in[3];
    const float* W2        = (const float*)d_in[4];
    const float* b2        = (const float*)d_in[5];
    const float* raw_alpha = (const float*)d_in[6];
    const int*   e2g       = (const int*)d_in[7];
    int T = in_sizes[7];

    static cudaStream_t s1 = nullptr, s2 = nullptr;
    static cudaEvent_t  eRoot = nullptr, eW1 = nullptr, eW2 = nullptr;
    static bool smem_set = false;
    if (!s1) {
        cudaStreamCreateWithFlags(&s1, cudaStreamNonBlocking);
        cudaStreamCreateWithFlags(&s2, cudaStreamNonBlocking);
        cudaEventCreateWithFlags(&eRoot, cudaEventDisableTiming);
        cudaEventCreateWithFlags(&eW1,   cudaEventDisableTiming);
        cudaEventCreateWithFlags(&eW2,   cudaEventDisableTiming);
    }
    constexpr int SMEM_GEMM = (64 + 128) * 80 * 3;   // 46080 B
    if (!smem_set) {
        cudaFuncSetAttribute(gemm_kernel<DDIM, false>,
                             cudaFuncAttributeMaxDynamicSharedMemorySize, SMEM_GEMM);
        cudaFuncSetAttribute(gemm_kernel<HDIM, true>,
                             cudaFuncAttributeMaxDynamicSharedMemorySize, SMEM_GEMM);
        smem_set = true;
    }

    // fork
    cudaEventRecord(eRoot, 0);
    cudaStreamWaitEvent(s1, eRoot, 0);
    cudaStreamWaitEvent(s2, eRoot, 0);

    // side branches: weight transpose-converts (fp32 -> fp8 x32, [k][n] -> [n][k])
    transpose_cvt_kernel<<<dim3(HDIM / 32, DDIM / 32, NE), dim3(32, 8), 0, s1>>>(W1, DDIM, HDIM, 0);
    cudaEventRecord(eW1, s1);
    transpose_cvt_kernel<<<dim3(DDIM / 32, HDIM / 32, NE), dim3(32, 8), 0, s2>>>(W2, HDIM, DDIM, 1);
    cudaEventRecord(eW2, s2);

    // main branch
    prep_kernel<<<1, 256>>>(ids, e2g, raw_alpha, T);
    gather_kernel<<<768, 256>>>(x);

    cudaStreamWaitEvent(0, eW1, 0);
    gemm_kernel<DDIM, false><<<dim3(NTOK / 64, HDIM / 128, NE), 256, SMEM_GEMM>>>(b1, x);

    cudaStreamWaitEvent(0, eW2, 0);
    gemm_kernel<HDIM, true ><<<dim3(NTOK / 64, DDIM / 128, NE), 256, SMEM_GEMM>>>(b2, x);

    normalize_kernel<<<NTOK, 192>>>((float*)d_out);
}